// round 7
// baseline (speedup 1.0000x reference)
#include <cuda_runtime.h>

// Problem constants (fixed by the dataset)
#define B_   4
#define N_   4096
#define H_   16
#define D_   64
#define ROWS (B_ * N_ * H_)          // 262144 rows
#define SM_SCALE 0.125f              // 1/sqrt(64)
#define EPS_ 1e-9f

// 16 lanes per row, float4 per lane (16*4 = 64 = D). 256 threads = 16 rows/block.
// Default cache policy everywhere: harness times back-to-back graph replays,
// and default caching picks up incidental cross-replay L2 hits that
// streaming (evict-first) hints measurably forfeit (R2-R6 evidence).
__global__ __launch_bounds__(256, 8)
void hier_attn_kernel(const float* __restrict__ Qp,
                      const float* __restrict__ Kp,
                      const float* __restrict__ Vp,
                      const float* __restrict__ Kc,
                      const float* __restrict__ Vc,
                      float* __restrict__ out,
                      float* __restrict__ w_out) {
    const int tid = blockIdx.x * blockDim.x + threadIdx.x;
    const int row = tid >> 4;          // global row = (b*N + n)*H + h
    const int l   = tid & 15;          // lane within the row group

    const int h  = row & (H_ - 1);
    const int bn = row >> 4;           // b*N + n   (H_ = 16)
    const int n  = bn & (N_ - 1);
    const int b  = bn >> 12;           // N_ = 4096

    // parent-layout: [b, n, h, d] -> row * D
    const int p_off  = row * D_ + l * 4;
    // child-layout: [b, 2n+c, h, d]
    const int c0_off = (((b * (2 * N_) + 2 * n) * H_) + h) * D_ + l * 4;
    const int c1_off = c0_off + H_ * D_;

    // 7 front-batched LDG.128 loads (default cache policy)
    const float4 q   = *reinterpret_cast<const float4*>(Qp + p_off);
    const float4 kp  = *reinterpret_cast<const float4*>(Kp + p_off);
    const float4 kc0 = *reinterpret_cast<const float4*>(Kc + c0_off);
    const float4 kc1 = *reinterpret_cast<const float4*>(Kc + c1_off);
    const float4 vp  = *reinterpret_cast<const float4*>(Vp + p_off);
    const float4 vc0 = *reinterpret_cast<const float4*>(Vc + c0_off);
    const float4 vc1 = *reinterpret_cast<const float4*>(Vc + c1_off);

    // Three partial dot products (4 elements per lane)
    float s0 = q.x * kp.x  + q.y * kp.y  + q.z * kp.z  + q.w * kp.w;
    float s1 = q.x * kc0.x + q.y * kc0.y + q.z * kc0.z + q.w * kc0.w;
    float s2 = q.x * kc1.x + q.y * kc1.y + q.z * kc1.z + q.w * kc1.w;

    // Butterfly reduction within each 16-lane group
    #pragma unroll
    for (int m = 8; m > 0; m >>= 1) {
        s0 += __shfl_xor_sync(0xFFFFFFFFu, s0, m);
        s1 += __shfl_xor_sync(0xFFFFFFFFu, s1, m);
        s2 += __shfl_xor_sync(0xFFFFFFFFu, s2, m);
    }

    s0 *= SM_SCALE; s1 *= SM_SCALE; s2 *= SM_SCALE;

    // 3-way softmax with +eps in denominator (matches reference)
    const float mx = fmaxf(s0, fmaxf(s1, s2));
    const float e0 = __expf(s0 - mx);
    const float e1 = __expf(s1 - mx);
    const float e2 = __expf(s2 - mx);
    const float inv = 1.0f / (e0 + e1 + e2 + EPS_);
    const float w0 = e0 * inv;
    const float w1 = e1 * inv;
    const float w2 = e2 * inv;

    // Weighted V combine, coalesced STG.128 store
    float4 o;
    o.x = w0 * vp.x + w1 * vc0.x + w2 * vc1.x;
    o.y = w0 * vp.y + w1 * vc0.y + w2 * vc1.y;
    o.z = w0 * vp.z + w1 * vc0.z + w2 * vc1.z;
    o.w = w0 * vp.w + w1 * vc0.w + w2 * vc1.w;
    *reinterpret_cast<float4*>(out + p_off) = o;

    // w output: [b,n,h,3] raveled after out
    if (l < 3) {
        const float wv = (l == 0) ? w0 : (l == 1) ? w1 : w2;
        w_out[row * 3 + l] = wv;
    }
}

extern "C" void kernel_launch(void* const* d_in, const int* in_sizes, int n_in,
                              void* d_out, int out_size) {
    const float* Qp = (const float*)d_in[0];
    const float* Kp = (const float*)d_in[1];
    const float* Vp = (const float*)d_in[2];
    const float* Kc = (const float*)d_in[3];
    const float* Vc = (const float*)d_in[4];

    float* out   = (float*)d_out;
    float* w_out = out + (size_t)ROWS * D_;   // w follows out in the output buffer

    const int threads = 256;                   // 16 rows per block
    const int blocks  = (ROWS * 16) / threads; // 16384
    hier_attn_kernel<<<blocks, threads>>>(Qp, Kp, Vp, Kc, Vc, out, w_out);
}

// round 8
// speedup vs baseline: 1.0204x; 1.0204x over previous
#include <cuda_runtime.h>

// Problem constants (fixed by the dataset)
#define B_   4
#define N_   4096
#define H_   16
#define D_   64
#define ROWS (B_ * N_ * H_)          // 262144 rows, one warp each
#define SM_SCALE 0.125f              // 1/sqrt(64)
#define EPS_ 1e-9f

// R1 reproduction: one warp per row, float2 per lane, default cache policy.
// R1-R7 evidence: harness time is HBM-drain-rate bound at natural clocks;
// SM-time deltas are invisible. This config produced the best harness sample
// (78.56); re-measuring to separate structural effect from noise.
__global__ __launch_bounds__(256, 8)
void hier_attn_kernel(const float* __restrict__ Qp,
                      const float* __restrict__ Kp,
                      const float* __restrict__ Vp,
                      const float* __restrict__ Kc,
                      const float* __restrict__ Vc,
                      float* __restrict__ out,
                      float* __restrict__ w_out) {
    const int gwarp = (blockIdx.x * blockDim.x + threadIdx.x) >> 5;
    const int lane  = threadIdx.x & 31;
    if (gwarp >= ROWS) return;

    // gwarp = (b*N + n)*H + h
    const int h  = gwarp % H_;
    const int bn = gwarp / H_;      // b*N + n
    const int n  = bn % N_;
    const int b  = bn / N_;

    // parent-layout offset: [b, n, h, d] with d contiguous -> gwarp * D
    const size_t p_off  = (size_t)gwarp * D_;
    // child-layout offset: [b, 2n+c, h, d]
    const size_t c0_off = (((size_t)b * (2 * N_) + 2 * n) * H_ + h) * D_;
    const size_t c1_off = c0_off + (size_t)H_ * D_;

    // All 7 vector loads front-batched (float2 per lane => 256B coalesced each)
    const float2 q   = reinterpret_cast<const float2*>(Qp + p_off)[lane];
    const float2 kp  = reinterpret_cast<const float2*>(Kp + p_off)[lane];
    const float2 kc0 = reinterpret_cast<const float2*>(Kc + c0_off)[lane];
    const float2 kc1 = reinterpret_cast<const float2*>(Kc + c1_off)[lane];
    const float2 vp  = reinterpret_cast<const float2*>(Vp + p_off)[lane];
    const float2 vc0 = reinterpret_cast<const float2*>(Vc + c0_off)[lane];
    const float2 vc1 = reinterpret_cast<const float2*>(Vc + c1_off)[lane];

    // Three partial dot products
    float s0 = q.x * kp.x  + q.y * kp.y;
    float s1 = q.x * kc0.x + q.y * kc0.y;
    float s2 = q.x * kc1.x + q.y * kc1.y;

    // Butterfly reduction across the warp (all lanes end with full sums)
    #pragma unroll
    for (int m = 16; m > 0; m >>= 1) {
        s0 += __shfl_xor_sync(0xFFFFFFFFu, s0, m);
        s1 += __shfl_xor_sync(0xFFFFFFFFu, s1, m);
        s2 += __shfl_xor_sync(0xFFFFFFFFu, s2, m);
    }

    s0 *= SM_SCALE;
    s1 *= SM_SCALE;
    s2 *= SM_SCALE;

    // 3-way softmax with +eps in denominator (matches reference)
    const float mx = fmaxf(s0, fmaxf(s1, s2));
    const float e0 = expf(s0 - mx);
    const float e1 = expf(s1 - mx);
    const float e2 = expf(s2 - mx);
    const float inv = 1.0f / (e0 + e1 + e2 + EPS_);
    const float w0 = e0 * inv;
    const float w1 = e1 * inv;
    const float w2 = e2 * inv;

    // Weighted V combine, coalesced float2 store
    float2 o;
    o.x = w0 * vp.x + w1 * vc0.x + w2 * vc1.x;
    o.y = w0 * vp.y + w1 * vc0.y + w2 * vc1.y;
    reinterpret_cast<float2*>(out + p_off)[lane] = o;

    // w output: [b,n,h,3] raveled after out
    if (lane < 3) {
        const float wv = (lane == 0) ? w0 : (lane == 1) ? w1 : w2;
        w_out[(size_t)gwarp * 3 + lane] = wv;
    }
}

extern "C" void kernel_launch(void* const* d_in, const int* in_sizes, int n_in,
                              void* d_out, int out_size) {
    const float* Qp = (const float*)d_in[0];
    const float* Kp = (const float*)d_in[1];
    const float* Vp = (const float*)d_in[2];
    const float* Kc = (const float*)d_in[3];
    const float* Vc = (const float*)d_in[4];

    float* out   = (float*)d_out;
    float* w_out = out + (size_t)ROWS * D_;   // w follows out in the output buffer

    const int threads = 256;                  // 8 warps/block
    const int blocks  = (ROWS * 32) / threads; // 32768
    hier_attn_kernel<<<blocks, threads>>>(Qp, Kp, Vp, Kc, Vc, out, w_out);
}